// round 2
// baseline (speedup 1.0000x reference)
#include <cuda_runtime.h>

#define B_ 4
#define H_ 8
#define N_ 256
#define DQ 80
#define DNK 64
#define DEK 16
#define DV 64
#define TQ 16
#define NTHREADS 256
#define ATT_STRIDE 257   // pad so phase-D row reads hit distinct banks

__global__ __launch_bounds__(NTHREADS, 2)
void edge_attn_kernel(const float* __restrict__ q,
                      const float* __restrict__ nk,
                      const float* __restrict__ ek,
                      const float* __restrict__ v,
                      const int*   __restrict__ mask,
                      float* __restrict__ out,       // [B,H,N,DV]
                      float* __restrict__ attn_out)  // [B,H,N,N]
{
    __shared__ float s_qT[DQ * TQ];            // q tile, transposed: [d][qq]
    __shared__ float s_attn[TQ * ATT_STRIDE];  // logits -> probs

    const int tid = threadIdx.x;
    const int qt  = blockIdx.x;
    const int h   = blockIdx.y;
    const int b   = blockIdx.z;
    const int bh  = b * H_ + h;
    const int q0  = qt * TQ;
    const int k   = tid;  // one thread per key

    // ---- Phase A: load q tile transposed into smem (coalesced gmem reads) ----
    const float* qbase = q + (size_t)(bh * N_ + q0) * DQ;
    for (int i = tid; i < TQ * DQ; i += NTHREADS) {
        int qq = i / DQ;
        int d  = i - qq * DQ;
        s_qT[d * TQ + qq] = qbase[qq * DQ + d];
    }

    // ---- load this thread's nk row into registers (L2-resident, 256B/thread) ----
    float4 nkr[16];
    const float4* nkp = (const float4*)(nk + (size_t)(bh * N_ + k) * DNK);
#pragma unroll
    for (int i = 0; i < 16; i++) nkr[i] = nkp[i];

    __syncthreads();

    // ---- Phase B: logits for all TQ query rows against key k ----
    float acc[TQ];
#pragma unroll
    for (int qq = 0; qq < TQ; qq++) acc[qq] = 0.f;

    const float4* sqT4 = (const float4*)s_qT;  // row d = 4 float4s at index d*4
#pragma unroll
    for (int i = 0; i < 16; i++) {
        float4 nv4 = nkr[i];
#pragma unroll
        for (int c = 0; c < 4; c++) {
            int d = i * 4 + c;
            float nv = (c == 0) ? nv4.x : (c == 1) ? nv4.y : (c == 2) ? nv4.z : nv4.w;
            float4 q0v = sqT4[d * 4 + 0];
            float4 q1v = sqT4[d * 4 + 1];
            float4 q2v = sqT4[d * 4 + 2];
            float4 q3v = sqT4[d * 4 + 3];
            acc[0]  += nv * q0v.x;  acc[1]  += nv * q0v.y;
            acc[2]  += nv * q0v.z;  acc[3]  += nv * q0v.w;
            acc[4]  += nv * q1v.x;  acc[5]  += nv * q1v.y;
            acc[6]  += nv * q1v.z;  acc[7]  += nv * q1v.w;
            acc[8]  += nv * q2v.x;  acc[9]  += nv * q2v.y;
            acc[10] += nv * q2v.z;  acc[11] += nv * q2v.w;
            acc[12] += nv * q3v.x;  acc[13] += nv * q3v.y;
            acc[14] += nv * q3v.z;  acc[15] += nv * q3v.w;
        }
    }

    // edge term: ek[b,h,q,k,0:16] — the single cold HBM stream, read once
    const float4* ekp = (const float4*)(ek + (size_t)((bh * N_ + q0) * N_ + k) * DEK);
#pragma unroll
    for (int qq = 0; qq < TQ; qq++) {
        const float4* e = ekp + qq * (N_ * DEK / 4);
        float4 e0 = e[0], e1 = e[1], e2 = e[2], e3 = e[3];
        float s;
        s  = e0.x * s_qT[(DNK +  0) * TQ + qq];
        s += e0.y * s_qT[(DNK +  1) * TQ + qq];
        s += e0.z * s_qT[(DNK +  2) * TQ + qq];
        s += e0.w * s_qT[(DNK +  3) * TQ + qq];
        s += e1.x * s_qT[(DNK +  4) * TQ + qq];
        s += e1.y * s_qT[(DNK +  5) * TQ + qq];
        s += e1.z * s_qT[(DNK +  6) * TQ + qq];
        s += e1.w * s_qT[(DNK +  7) * TQ + qq];
        s += e2.x * s_qT[(DNK +  8) * TQ + qq];
        s += e2.y * s_qT[(DNK +  9) * TQ + qq];
        s += e2.z * s_qT[(DNK + 10) * TQ + qq];
        s += e2.w * s_qT[(DNK + 11) * TQ + qq];
        s += e3.x * s_qT[(DNK + 12) * TQ + qq];
        s += e3.y * s_qT[(DNK + 13) * TQ + qq];
        s += e3.z * s_qT[(DNK + 14) * TQ + qq];
        s += e3.w * s_qT[(DNK + 15) * TQ + qq];
        acc[qq] += s;
    }

    // mask + temperature, write logits to smem (conflict-free: consecutive k)
    const int* mrow = mask + (b * N_ + q0) * N_ + k;
#pragma unroll
    for (int qq = 0; qq < TQ; qq++) {
        float logit = acc[qq] * 0.125f;
        int m = mrow[qq * N_];
        s_attn[qq * ATT_STRIDE + k] = (m == 0) ? -1000000000.0f : logit;
    }
    __syncthreads();

    // ---- Phase C: softmax, one warp per 2 rows; write attn to gmem ----
    {
        const int warp = tid >> 5, lane = tid & 31;
        float* attn_g = attn_out + (size_t)(bh * N_ + q0) * N_;
#pragma unroll
        for (int r = 0; r < 2; r++) {
            int qq = warp * 2 + r;
            float* row = s_attn + qq * ATT_STRIDE;
            float vals[8];
            float mx = -3.4e38f;
#pragma unroll
            for (int i = 0; i < 8; i++) {
                vals[i] = row[lane + 32 * i];
                mx = fmaxf(mx, vals[i]);
            }
#pragma unroll
            for (int off = 16; off; off >>= 1)
                mx = fmaxf(mx, __shfl_xor_sync(0xffffffffu, mx, off));
            float sum = 0.f;
#pragma unroll
            for (int i = 0; i < 8; i++) {
                float e = __expf(vals[i] - mx);
                vals[i] = e;
                sum += e;
            }
#pragma unroll
            for (int off = 16; off; off >>= 1)
                sum += __shfl_xor_sync(0xffffffffu, sum, off);
            float inv = 1.0f / sum;
#pragma unroll
            for (int i = 0; i < 8; i++) {
                float p = vals[i] * inv;
                row[lane + 32 * i] = p;
                attn_g[qq * N_ + lane + 32 * i] = p;
            }
        }
    }
    __syncthreads();

    // ---- Phase D: out[q][d] = sum_k attn[q][k] * v[k][d] ----
    {
        const int dg = tid & 15;   // 4 dims each
        const int qq = tid >> 4;   // 1 q-row each
        const float* vrow = v + (size_t)(bh * N_) * DV + dg * 4;
        const float* arow = s_attn + qq * ATT_STRIDE;
        float4 o = make_float4(0.f, 0.f, 0.f, 0.f);
#pragma unroll 4
        for (int kk = 0; kk < N_; kk++) {
            float a = arow[kk];                              // broadcast LDS
            float4 vv = *(const float4*)(vrow + kk * DV);    // L1-resident
            o.x += a * vv.x; o.y += a * vv.y;
            o.z += a * vv.z; o.w += a * vv.w;
        }
        float4* op = (float4*)(out + (size_t)(bh * N_ + q0 + qq) * DV + dg * 4);
        *op = o;
    }
}

extern "C" void kernel_launch(void* const* d_in, const int* in_sizes, int n_in,
                              void* d_out, int out_size)
{
    const float* q    = (const float*)d_in[0];
    const float* nk   = (const float*)d_in[1];
    const float* ek   = (const float*)d_in[2];
    const float* v    = (const float*)d_in[3];
    const int*   mask = (const int*)d_in[4];

    float* out  = (float*)d_out;                         // [4,8,256,64]
    float* attn = out + (size_t)B_ * H_ * N_ * DV;       // [4,8,256,256]

    dim3 grid(N_ / TQ, H_, B_);
    edge_attn_kernel<<<grid, NTHREADS>>>(q, nk, ek, v, mask, out, attn);
}